// round 7
// baseline (speedup 1.0000x reference)
#include <cuda_runtime.h>
#include <cuda_bf16.h>
#include <cstdint>

#define N_NODES 50000
#define N_PAD   50048
#define N_EDGES 800000
#define D_F 256
#define D_H 512
#define D_O 256
#define D_AB 1024

// ---------------- scratch (static device allocations; no cudaMalloc) -------
__device__ uint32_t g_Xhi[N_PAD * (D_F / 2)];
__device__ uint32_t g_Xlo[N_PAD * (D_F / 2)];
__device__ uint32_t g_WT1hi[D_AB * (D_F / 2)];
__device__ uint32_t g_WT1lo[D_AB * (D_F / 2)];
__device__ uint32_t g_WT2hi[D_O * (D_H / 2)];
__device__ uint32_t g_WT2lo[D_O * (D_H / 2)];
__device__ float    g_bias1[D_AB];
__device__ float    g_AB[N_NODES * D_AB];
__device__ uint32_t g_Shi[N_PAD * (D_H / 2)];
__device__ uint32_t g_Slo[N_PAD * (D_H / 2)];
__device__ int      g_counts[N_NODES];
__device__ int      g_offsets[N_NODES + 1];
__device__ int      g_cursor[N_NODES];
__device__ int      g_scol[N_EDGES];
__device__ int      g_idx64;

// ---------------- helpers ---------------------------------------------------
__device__ __forceinline__ void split2(float v0, float v1, uint32_t& hw, uint32_t& lw) {
    __nv_bfloat16 h0 = __float2bfloat16_rn(v0);
    __nv_bfloat16 h1 = __float2bfloat16_rn(v1);
    float r0 = v0 - __bfloat162float(h0);
    float r1 = v1 - __bfloat162float(h1);
    __nv_bfloat16 l0 = __float2bfloat16_rn(r0);
    __nv_bfloat16 l1 = __float2bfloat16_rn(r1);
    hw = (uint32_t)__bfloat16_as_ushort(h0) | ((uint32_t)__bfloat16_as_ushort(h1) << 16);
    lw = (uint32_t)__bfloat16_as_ushort(l0) | ((uint32_t)__bfloat16_as_ushort(l1) << 16);
}
__device__ __forceinline__ void mma_bf16(float* d, const uint32_t* a, const uint32_t* b) {
    asm volatile(
        "mma.sync.aligned.m16n8k16.row.col.f32.bf16.bf16.f32 "
        "{%0,%1,%2,%3}, {%4,%5,%6,%7}, {%8,%9}, {%0,%1,%2,%3};\n"
        : "+f"(d[0]), "+f"(d[1]), "+f"(d[2]), "+f"(d[3])
        : "r"(a[0]), "r"(a[1]), "r"(a[2]), "r"(a[3]), "r"(b[0]), "r"(b[1]));
}
__device__ __forceinline__ void ldsm_x4(uint32_t* r, uint32_t saddr) {
    asm volatile("ldmatrix.sync.aligned.m8n8.x4.shared.b16 {%0,%1,%2,%3}, [%4];"
                 : "=r"(r[0]), "=r"(r[1]), "=r"(r[2]), "=r"(r[3]) : "r"(saddr));
}
__device__ __forceinline__ uint32_t smem_u32(const void* p) {
    uint32_t a;
    asm("{ .reg .u64 t; cvta.to.shared.u64 t, %1; cvt.u32.u64 %0, t; }" : "=r"(a) : "l"(p));
    return a;
}
#define CP16(dst, src) \
    asm volatile("cp.async.cg.shared.global [%0], [%1], 16;" :: "r"(dst), "l"(src))
#define CP_COMMIT()  asm volatile("cp.async.commit_group;" ::: "memory")
#define CP_WAIT(n)   asm volatile("cp.async.wait_group %0;" :: "n"(n) : "memory")

// ---------------- edge-index dtype detection -------------------------------
__global__ void detect_dtype_kernel(const unsigned* ei) {
    unsigned acc = 0;
    for (int k = threadIdx.x; k < 512; k += 32) acc |= ei[2 * k + 1];
    #pragma unroll
    for (int o = 16; o > 0; o >>= 1) acc |= __shfl_xor_sync(0xFFFFFFFFu, acc, o);
    if (threadIdx.x == 0) g_idx64 = (acc == 0) ? 1 : 0;
}
__device__ __forceinline__ int load_eidx(const void* ei, int is64, long long pos) {
    return is64 ? (int)((const long long*)ei)[pos] : ((const int*)ei)[pos];
}

// ---------------- x split ----------------------------------------------------
__global__ void split_x_kernel(const float* __restrict__ x) {
    int gid = blockIdx.x * blockDim.x + threadIdx.x;
    if (gid >= N_NODES * 32) return;
    int row = gid >> 5, ch = gid & 31;
    const float4* p = (const float4*)(x + (size_t)row * D_F + ch * 8);
    float4 v0 = p[0], v1 = p[1];
    uint4 h, l;
    split2(v0.x, v0.y, h.x, l.x); split2(v0.z, v0.w, h.y, l.y);
    split2(v1.x, v1.y, h.z, l.z); split2(v1.z, v1.w, h.w, l.w);
    *(uint4*)(g_Xhi + (size_t)row * (D_F / 2) + ch * 4) = h;
    *(uint4*)(g_Xlo + (size_t)row * (D_F / 2) + ch * 4) = l;
}

// ---------------- weight prep ------------------------------------------------
__global__ void build_w1t_kernel(const float* __restrict__ W1, const float* __restrict__ b1) {
    int idx = blockIdx.x * blockDim.x + threadIdx.x;
    if (idx < D_AB * (D_F / 2)) {
        int n  = idx >> 7;
        int kw = idx & 127;
        int k0 = kw * 2;
        float v0, v1;
        if (n < D_H) {
            v0 = W1[k0 * D_H + n]       - W1[(k0 + D_F) * D_H + n];
            v1 = W1[(k0 + 1) * D_H + n] - W1[(k0 + 1 + D_F) * D_H + n];
        } else {
            v0 = W1[(k0 + D_F) * D_H + (n - D_H)];
            v1 = W1[(k0 + 1 + D_F) * D_H + (n - D_H)];
        }
        uint32_t hw, lw;
        split2(v0, v1, hw, lw);
        g_WT1hi[idx] = hw; g_WT1lo[idx] = lw;
    }
    if (idx < D_AB) g_bias1[idx] = (idx < D_H) ? b1[idx] : 0.f;
}
__global__ void build_w2t_kernel(const float* __restrict__ W2) {
    int idx = blockIdx.x * blockDim.x + threadIdx.x;
    if (idx < D_O * (D_H / 2)) {
        int n  = idx >> 8;
        int kw = idx & 255;
        float v0 = W2[(2 * kw) * D_O + n];
        float v1 = W2[(2 * kw + 1) * D_O + n];
        uint32_t hw, lw;
        split2(v0, v1, hw, lw);
        g_WT2hi[idx] = hw; g_WT2lo[idx] = lw;
    }
}

// ---------------- counting sort ----------------------------------------------
__global__ void zero_counts_kernel() {
    int i = blockIdx.x * blockDim.x + threadIdx.x;
    if (i < N_NODES) g_counts[i] = 0;
}
__global__ void hist_kernel(const void* __restrict__ ei) {
    int e = blockIdx.x * blockDim.x + threadIdx.x;
    if (e >= N_EDGES) return;
    int r = load_eidx(ei, g_idx64, e);
    atomicAdd(&g_counts[r], 1);
}
__global__ void scan_kernel() {
    __shared__ int sh[1024];
    const int PER = 49;
    int t = threadIdx.x;
    int base = t * PER;
    int sum = 0;
    for (int j = 0; j < PER; j++) {
        int idx = base + j;
        if (idx < N_NODES) sum += g_counts[idx];
    }
    sh[t] = sum;
    __syncthreads();
    #pragma unroll
    for (int off = 1; off < 1024; off <<= 1) {
        int add = (t >= off) ? sh[t - off] : 0;
        __syncthreads();
        sh[t] += add;
        __syncthreads();
    }
    int run = sh[t] - sum;
    for (int j = 0; j < PER; j++) {
        int idx = base + j;
        if (idx < N_NODES) {
            g_offsets[idx] = run;
            g_cursor[idx]  = run;
            run += g_counts[idx];
        }
    }
    if (t == 1023) g_offsets[N_NODES] = run;
}
__global__ void scatter_kernel(const void* __restrict__ ei) {
    int e = blockIdx.x * blockDim.x + threadIdx.x;
    if (e >= N_EDGES) return;
    int is64 = g_idx64;
    int r = load_eidx(ei, is64, e);
    int c = load_eidx(ei, is64, (long long)N_EDGES + e);
    int pos = atomicAdd(&g_cursor[r], 1);
    g_scol[pos] = c;
}

// =================== bf16 3-term GEMM: swizzled smem, 3-stage cp.async =====
// Tile row = 128 B: words 0-15 hi, 16-31 lo, 16B-chunk swizzle c^(row&7).
// A tile 16 KB, B tile 16 KB -> 32 KB/stage, 3 stages.
#define KWC 16
#define STAGE_B 32768
#define TILE_B  16384
#define CSTRIDE 132
#define GEMM_DYNSMEM (3 * STAGE_B)       // 98304 B

__global__ void __launch_bounds__(256, 2) tc_gemm_kernel(
    const uint32_t* __restrict__ Ahi, const uint32_t* __restrict__ Alo,
    const uint32_t* __restrict__ Bhi, const uint32_t* __restrict__ Blo,
    float* __restrict__ C, int M, int K, int ldc,
    const float* __restrict__ bias, int mode)
{
    extern __shared__ uint32_t smw[];
    int tid = threadIdx.x;
    int wid = tid >> 5;
    int lane = tid & 31;
    int warpM = wid & 1;
    int warpN = wid >> 1;
    int blockRow = blockIdx.y * 128;
    int blockCol = blockIdx.x * 128;
    const int Kw = K >> 1;
    const int nch = K >> 5;

    float acc[4][4][4];
    #pragma unroll
    for (int mt = 0; mt < 4; mt++)
        #pragma unroll
        for (int nt = 0; nt < 4; nt++)
            #pragma unroll
            for (int r = 0; r < 4; r++) acc[mt][nt][r] = 0.f;

    uint32_t sbase = smem_u32(smw);

    // cp.async mapping: thread -> (row = tid>>1, 4 chunks of hi or lo)
    int ldRow = tid >> 1;
    int ldLo  = tid & 1;                       // 0: hi chunks 0-3, 1: lo chunks 4-7
    size_t aOff = (size_t)(blockRow + ldRow) * Kw;
    size_t bOff = (size_t)(blockCol + ldRow) * Kw;
    uint32_t dRowA = (uint32_t)ldRow * 128;
    uint32_t dRowB = TILE_B + dRowA;
    int rsel = ldRow & 7;

    auto issue = [&](int c, int stage) {
        uint32_t sb = sbase + (uint32_t)stage * STAGE_B;
        const uint32_t* srcA = (ldLo ? Alo : Ahi) + aOff + (size_t)c * KWC;
        const uint32_t* srcB = (ldLo ? Blo : Bhi) + bOff + (size_t)c * KWC;
        #pragma unroll
        for (int q = 0; q < 4; q++) {
            int chunk = ldLo * 4 + q;
            uint32_t d = ((uint32_t)(chunk ^ rsel)) * 16;
            CP16(sb + dRowA + d, srcA + q * 4);
            CP16(sb + dRowB + d, srcB + q * 4);
        }
        CP_COMMIT();
    };

    issue(0, 0);
    if (nch > 1) issue(1, 1);

    // fragment base addresses (hi, ks=0, mt/p = 0); variants via XOR/offset
    int rowA = warpM * 64 + (lane & 7) + ((lane >> 3) & 1) * 8;
    int rowB = warpN * 32 + (lane & 7) + (lane >> 4) * 8;
    uint32_t cA = (uint32_t)(lane >> 4) ^ (uint32_t)(rowA & 7);         // chunk' for A hi ks0
    uint32_t cB = (uint32_t)((lane >> 3) & 1) ^ (uint32_t)(rowB & 7);   // chunk' for B hi ks0
    uint32_t aAddr = sbase + (uint32_t)rowA * 128 + cA * 16;
    uint32_t bAddr = sbase + TILE_B + (uint32_t)rowB * 128 + cB * 16;

    int stage = 0;
    for (int c = 0; c < nch; c++) {
        CP_WAIT(1);
        __syncthreads();

        uint32_t sOff = (uint32_t)stage * STAGE_B;
        #pragma unroll
        for (int ks = 0; ks < 2; ks++) {
            uint32_t ksx = (uint32_t)ks << 5;       // chunk' ^= ks*2 -> addr ^ 0x20
            uint32_t ahi[4][4], alo[4][4], bhi[2][4], blo[2][4];
            #pragma unroll
            for (int mt = 0; mt < 4; mt++) {
                uint32_t a = (aAddr + sOff + mt * 2048) ^ ksx;
                ldsm_x4(ahi[mt], a);
                ldsm_x4(alo[mt], a ^ 0x40);
            }
            #pragma unroll
            for (int p = 0; p < 2; p++) {
                uint32_t b = (bAddr + sOff + p * 2048) ^ ksx;
                ldsm_x4(bhi[p], b);
                ldsm_x4(blo[p], b ^ 0x40);
            }
            #pragma unroll
            for (int mt = 0; mt < 4; mt++)
                #pragma unroll
                for (int nt = 0; nt < 4; nt++) {
                    const uint32_t* bh = &bhi[nt >> 1][(nt & 1) * 2];
                    const uint32_t* bl = &blo[nt >> 1][(nt & 1) * 2];
                    mma_bf16(acc[mt][nt], ahi[mt], bh);
                    mma_bf16(acc[mt][nt], ahi[mt], bl);
                    mma_bf16(acc[mt][nt], alo[mt], bh);
                }
        }

        if (c + 2 < nch) {
            int ns = stage + 2; if (ns >= 3) ns -= 3;
            issue(c + 2, ns);
        }
        if (++stage == 3) stage = 0;
    }

    // ---- staged epilogue ----
    __syncthreads();
    float* cs = (float*)smw;
    #pragma unroll
    for (int mt = 0; mt < 4; mt++) {
        int r0 = warpM * 64 + mt * 16 + (lane >> 2);
        #pragma unroll
        for (int nt = 0; nt < 4; nt++) {
            int col = warpN * 32 + nt * 8 + (lane & 3) * 2;
            *(float2*)(cs + r0 * CSTRIDE + col) = make_float2(acc[mt][nt][0], acc[mt][nt][1]);
            *(float2*)(cs + (r0 + 8) * CSTRIDE + col) = make_float2(acc[mt][nt][2], acc[mt][nt][3]);
        }
    }
    __syncthreads();
    #pragma unroll
    for (int kk = 0; kk < 16; kk++) {
        int idx = tid + kk * 256;
        int row = idx >> 5;
        int c4 = (idx & 31) * 4;
        int gr = blockRow + row;
        if (gr < M) {
            float4 v = *(float4*)(cs + row * CSTRIDE + c4);
            float4 bv = *(const float4*)(bias + blockCol + c4);
            if (mode == 0) {
                v.x += bv.x; v.y += bv.y; v.z += bv.z; v.w += bv.w;
            } else {
                float degf = (float)(g_offsets[gr + 1] - g_offsets[gr]);
                v.x += degf * bv.x; v.y += degf * bv.y;
                v.z += degf * bv.z; v.w += degf * bv.w;
            }
            *(float4*)(C + (size_t)gr * ldc + blockCol + c4) = v;
        }
    }
}

// ---------------- aggregation: warp per node --------------------------------
__global__ void __launch_bounds__(256) aggregate_kernel() {
    int gw = (blockIdx.x * blockDim.x + threadIdx.x) >> 5;
    int lane = threadIdx.x & 31;
    if (gw >= N_NODES) return;

    const float4* Ai = (const float4*)(g_AB + (size_t)gw * D_AB) + lane * 4;
    float4 a0 = Ai[0], a1 = Ai[1], a2 = Ai[2], a3 = Ai[3];
    float4 s0 = make_float4(0, 0, 0, 0), s1 = s0, s2 = s0, s3 = s0;

    int beg = g_offsets[gw], end = g_offsets[gw + 1];
    for (int b = beg; b < end; b += 32) {
        int jv = (b + lane < end) ? g_scol[b + lane] : 0;
        int cnt = min(32, end - b);
        int t = 0;
        for (; t + 1 < cnt; t += 2) {
            int j0 = __shfl_sync(0xFFFFFFFFu, jv, t);
            int j1 = __shfl_sync(0xFFFFFFFFu, jv, t + 1);
            const float4* B0 = (const float4*)(g_AB + (size_t)j0 * D_AB + D_H) + lane * 4;
            const float4* B1 = (const float4*)(g_AB + (size_t)j1 * D_AB + D_H) + lane * 4;
            float4 p0 = B0[0], p1 = B0[1], p2 = B0[2], p3 = B0[3];
            float4 q0 = B1[0], q1 = B1[1], q2 = B1[2], q3 = B1[3];
            s0.x += fmaxf(a0.x + p0.x, 0.f) + fmaxf(a0.x + q0.x, 0.f);
            s0.y += fmaxf(a0.y + p0.y, 0.f) + fmaxf(a0.y + q0.y, 0.f);
            s0.z += fmaxf(a0.z + p0.z, 0.f) + fmaxf(a0.z + q0.z, 0.f);
            s0.w += fmaxf(a0.w + p0.w, 0.f) + fmaxf(a0.w + q0.w, 0.f);
            s1.x += fmaxf(a1.x + p1.x, 0.f) + fmaxf(a1.x + q1.x, 0.f);
            s1.y += fmaxf(a1.y + p1.y, 0.f) + fmaxf(a1.y + q1.y, 0.f);
            s1.z += fmaxf(a1.z + p1.z, 0.f) + fmaxf(a1.z + q1.z, 0.f);
            s1.w += fmaxf(a1.w + p1.w, 0.f) + fmaxf(a1.w + q1.w, 0.f);
            s2.x += fmaxf(a2.x + p2.x, 0.f) + fmaxf(a2.x + q2.x, 0.f);
            s2.y += fmaxf(a2.y + p2.y, 0.f) + fmaxf(a2.y + q2.y, 0.f);
            s2.z += fmaxf(a2.z + p2.z, 0.f) + fmaxf(a2.z + q2.z, 0.f);
            s2.w += fmaxf(a2.w + p2.w, 0.f) + fmaxf(a2.w + q2.w, 0.f);
            s3.x += fmaxf(a3.x + p3.x, 0.f) + fmaxf(a3.x + q3.x, 0.f);
            s3.y += fmaxf(a3.y + p3.y, 0.f) + fmaxf(a3.y + q3.y, 0.f);
            s3.z += fmaxf(a3.z + p3.z, 0.f) + fmaxf(a3.z + q3.z, 0.f);
            s3.w += fmaxf(a3.w + p3.w, 0.f) + fmaxf(a3.w + q3.w, 0.f);
        }
        if (t < cnt) {
            int j0 = __shfl_sync(0xFFFFFFFFu, jv, t);
            const float4* B0 = (const float4*)(g_AB + (size_t)j0 * D_AB + D_H) + lane * 4;
            float4 p0 = B0[0], p1 = B0[1], p2 = B0[2], p3 = B0[3];
            s0.x += fmaxf(a0.x + p0.x, 0.f); s0.y += fmaxf(a0.y + p0.y, 0.f);
            s0.z += fmaxf(a0.z + p0.z, 0.f); s0.w += fmaxf(a0.w + p0.w, 0.f);
            s1.x += fmaxf(a1.x + p1.x, 0.f); s1.y += fmaxf(a1.y + p1.y, 0.f);
            s1.z += fmaxf(a1.z + p1.z, 0.f); s1.w += fmaxf(a1.w + p1.w, 0.f);
            s2.x += fmaxf(a2.x + p2.x, 0.f); s2.y += fmaxf(a2.y + p2.y, 0.f);
            s2.z += fmaxf(a2.z + p2.z, 0.f); s2.w += fmaxf(a2.w + p2.w, 0.f);
            s3.x += fmaxf(a3.x + p3.x, 0.f); s3.y += fmaxf(a3.y + p3.y, 0.f);
            s3.z += fmaxf(a3.z + p3.z, 0.f); s3.w += fmaxf(a3.w + p3.w, 0.f);
        }
    }

    uint4 h0, h1, l0, l1;
    split2(s0.x, s0.y, h0.x, l0.x); split2(s0.z, s0.w, h0.y, l0.y);
    split2(s1.x, s1.y, h0.z, l0.z); split2(s1.z, s1.w, h0.w, l0.w);
    split2(s2.x, s2.y, h1.x, l1.x); split2(s2.z, s2.w, h1.y, l1.y);
    split2(s3.x, s3.y, h1.z, l1.z); split2(s3.z, s3.w, h1.w, l1.w);
    uint4* SH = (uint4*)(g_Shi + (size_t)gw * (D_H / 2)) + lane * 2;
    uint4* SL = (uint4*)(g_Slo + (size_t)gw * (D_H / 2)) + lane * 2;
    SH[0] = h0; SH[1] = h1;
    SL[0] = l0; SL[1] = l1;
}

// ---------------- launcher --------------------------------------------------
extern "C" void kernel_launch(void* const* d_in, const int* in_sizes, int n_in,
                              void* d_out, int out_size) {
    const float* x   = (const float*)d_in[0];
    const void*  ei  = d_in[1];
    const float* W1  = (const float*)d_in[2];
    const float* b1  = (const float*)d_in[3];
    const float* W2  = (const float*)d_in[4];
    const float* b2  = (const float*)d_in[5];
    float* out = (float*)d_out;

    cudaFuncSetAttribute(tc_gemm_kernel,
                         cudaFuncAttributeMaxDynamicSharedMemorySize, GEMM_DYNSMEM);

    float *gAB, *gB1;
    uint32_t *gXh, *gXl, *gW1h, *gW1l, *gW2h, *gW2l, *gSh, *gSl;
    cudaGetSymbolAddress((void**)&gAB,  g_AB);
    cudaGetSymbolAddress((void**)&gB1,  g_bias1);
    cudaGetSymbolAddress((void**)&gXh,  g_Xhi);
    cudaGetSymbolAddress((void**)&gXl,  g_Xlo);
    cudaGetSymbolAddress((void**)&gW1h, g_WT1hi);
    cudaGetSymbolAddress((void**)&gW1l, g_WT1lo);
    cudaGetSymbolAddress((void**)&gW2h, g_WT2hi);
    cudaGetSymbolAddress((void**)&gW2l, g_WT2lo);
    cudaGetSymbolAddress((void**)&gSh,  g_Shi);
    cudaGetSymbolAddress((void**)&gSl,  g_Slo);

    // launch order keeps GEMM1 in the 4th slot (ncu capture)
    detect_dtype_kernel<<<1, 32>>>((const unsigned*)ei);
    split_x_kernel<<<(N_NODES * 32 + 255) / 256, 256>>>(x);
    build_w1t_kernel<<<(D_AB * (D_F / 2) + 255) / 256, 256>>>(W1, b1);

    // GEMM1 (4th): AB[50000,1024] = x @ WT1^T (+bias_cat)
    {
        dim3 grid(D_AB / 128, N_PAD / 128);
        tc_gemm_kernel<<<grid, 256, GEMM_DYNSMEM>>>(
            gXh, gXl, gW1h, gW1l, gAB, N_NODES, D_F, D_AB, gB1, 0);
    }

    zero_counts_kernel<<<(N_NODES + 255) / 256, 256>>>();
    hist_kernel<<<(N_EDGES + 255) / 256, 256>>>(ei);
    scan_kernel<<<1, 1024>>>();
    scatter_kernel<<<(N_EDGES + 255) / 256, 256>>>(ei);

    aggregate_kernel<<<(N_NODES * 32 + 255) / 256, 256>>>();
    build_w2t_kernel<<<(D_O * (D_H / 2) + 255) / 256, 256>>>(W2);

    // GEMM2: out[50000,256] = S @ WT2^T + deg*b2
    {
        dim3 grid(D_O / 128, N_PAD / 128);
        tc_gemm_kernel<<<grid, 256, GEMM_DYNSMEM>>>(
            gSh, gSl, gW2h, gW2l, out, N_NODES, D_H, D_O, b2, 1);
    }
}

// round 8
// speedup vs baseline: 1.1050x; 1.1050x over previous
#include <cuda_runtime.h>
#include <cuda_bf16.h>
#include <cstdint>

#define N_NODES 50000
#define N_PAD   50048      // padded to multiple of 128
#define N_EDGES 800000
#define D_F 256
#define D_H 512
#define D_O 256
#define D_AB 1024

// ---------------- scratch (static device allocations; no cudaMalloc) -------
__device__ uint32_t g_Xhi[N_PAD * (D_F / 2)];      // packed bf16 x hi/lo
__device__ uint32_t g_Xlo[N_PAD * (D_F / 2)];
__device__ uint32_t g_WT1hi[D_AB * (D_F / 2)];
__device__ uint32_t g_WT1lo[D_AB * (D_F / 2)];
__device__ uint32_t g_WT2hi[D_O * (D_H / 2)];
__device__ uint32_t g_WT2lo[D_O * (D_H / 2)];
__device__ float    g_bias1[D_AB];
__device__ float    g_AB[N_NODES * D_AB];          // 204.8 MB fp32
__device__ uint32_t g_Shi[N_PAD * (D_H / 2)];
__device__ uint32_t g_Slo[N_PAD * (D_H / 2)];
__device__ int      g_counts[N_NODES];
__device__ int      g_offsets[N_NODES + 1];
__device__ int      g_cursor[N_NODES];
__device__ int      g_scol[N_EDGES];
__device__ int      g_idx64;

// ---------------- helpers ---------------------------------------------------
__device__ __forceinline__ void split2(float v0, float v1, uint32_t& hw, uint32_t& lw) {
    __nv_bfloat16 h0 = __float2bfloat16_rn(v0);
    __nv_bfloat16 h1 = __float2bfloat16_rn(v1);
    float r0 = v0 - __bfloat162float(h0);
    float r1 = v1 - __bfloat162float(h1);
    __nv_bfloat16 l0 = __float2bfloat16_rn(r0);
    __nv_bfloat16 l1 = __float2bfloat16_rn(r1);
    hw = (uint32_t)__bfloat16_as_ushort(h0) | ((uint32_t)__bfloat16_as_ushort(h1) << 16);
    lw = (uint32_t)__bfloat16_as_ushort(l0) | ((uint32_t)__bfloat16_as_ushort(l1) << 16);
}
__device__ __forceinline__ void mma_bf16(float* d, const uint32_t* a, const uint32_t* b) {
    asm volatile(
        "mma.sync.aligned.m16n8k16.row.col.f32.bf16.bf16.f32 "
        "{%0,%1,%2,%3}, {%4,%5,%6,%7}, {%8,%9}, {%0,%1,%2,%3};\n"
        : "+f"(d[0]), "+f"(d[1]), "+f"(d[2]), "+f"(d[3])
        : "r"(a[0]), "r"(a[1]), "r"(a[2]), "r"(a[3]), "r"(b[0]), "r"(b[1]));
}
__device__ __forceinline__ void ldsm_x4(uint32_t* r, uint32_t saddr) {
    asm volatile("ldmatrix.sync.aligned.m8n8.x4.shared.b16 {%0,%1,%2,%3}, [%4];"
                 : "=r"(r[0]), "=r"(r[1]), "=r"(r[2]), "=r"(r[3]) : "r"(saddr));
}
__device__ __forceinline__ uint32_t smem_u32(const void* p) {
    uint32_t a;
    asm("{ .reg .u64 t; cvta.to.shared.u64 t, %1; cvt.u32.u64 %0, t; }" : "=r"(a) : "l"(p));
    return a;
}
#define CP16(dst, src) \
    asm volatile("cp.async.cg.shared.global [%0], [%1], 16;" :: "r"(dst), "l"(src))
#define CP_COMMIT() asm volatile("cp.async.commit_group;" ::: "memory")
#define CP_WAIT0()  asm volatile("cp.async.wait_group 0;" ::: "memory")

// ---------------- edge-index dtype detection -------------------------------
__global__ void detect_dtype_kernel(const unsigned* ei) {
    unsigned acc = 0;
    for (int k = threadIdx.x; k < 512; k += 32) acc |= ei[2 * k + 1];
    #pragma unroll
    for (int o = 16; o > 0; o >>= 1) acc |= __shfl_xor_sync(0xFFFFFFFFu, acc, o);
    if (threadIdx.x == 0) g_idx64 = (acc == 0) ? 1 : 0;
}
__device__ __forceinline__ int load_eidx(const void* ei, int is64, long long pos) {
    return is64 ? (int)((const long long*)ei)[pos] : ((const int*)ei)[pos];
}

// ---------------- x split: fp32 -> packed bf16 hi/lo ------------------------
__global__ void split_x_kernel(const float* __restrict__ x) {
    int gid = blockIdx.x * blockDim.x + threadIdx.x;
    if (gid >= N_NODES * 32) return;
    int row = gid >> 5, ch = gid & 31;
    const float4* p = (const float4*)(x + (size_t)row * D_F + ch * 8);
    float4 v0 = p[0], v1 = p[1];
    uint4 h, l;
    split2(v0.x, v0.y, h.x, l.x); split2(v0.z, v0.w, h.y, l.y);
    split2(v1.x, v1.y, h.z, l.z); split2(v1.z, v1.w, h.w, l.w);
    *(uint4*)(g_Xhi + (size_t)row * (D_F / 2) + ch * 4) = h;
    *(uint4*)(g_Xlo + (size_t)row * (D_F / 2) + ch * 4) = l;
}

// ---------------- weight prep: K-major packed bf16 hi/lo -------------------
__global__ void build_w1t_kernel(const float* __restrict__ W1, const float* __restrict__ b1) {
    int idx = blockIdx.x * blockDim.x + threadIdx.x;
    if (idx < D_AB * (D_F / 2)) {
        int n  = idx >> 7;
        int kw = idx & 127;
        int k0 = kw * 2;
        float v0, v1;
        if (n < D_H) {
            v0 = W1[k0 * D_H + n]       - W1[(k0 + D_F) * D_H + n];
            v1 = W1[(k0 + 1) * D_H + n] - W1[(k0 + 1 + D_F) * D_H + n];
        } else {
            v0 = W1[(k0 + D_F) * D_H + (n - D_H)];
            v1 = W1[(k0 + 1 + D_F) * D_H + (n - D_H)];
        }
        uint32_t hw, lw;
        split2(v0, v1, hw, lw);
        g_WT1hi[idx] = hw; g_WT1lo[idx] = lw;
    }
    if (idx < D_AB) g_bias1[idx] = (idx < D_H) ? b1[idx] : 0.f;
}
__global__ void build_w2t_kernel(const float* __restrict__ W2) {
    int idx = blockIdx.x * blockDim.x + threadIdx.x;
    if (idx < D_O * (D_H / 2)) {
        int n  = idx >> 8;
        int kw = idx & 255;
        float v0 = W2[(2 * kw) * D_O + n];
        float v1 = W2[(2 * kw + 1) * D_O + n];
        uint32_t hw, lw;
        split2(v0, v1, hw, lw);
        g_WT2hi[idx] = hw; g_WT2lo[idx] = lw;
    }
}

// ---------------- counting sort of edges by center node --------------------
__global__ void zero_counts_kernel() {
    int i = blockIdx.x * blockDim.x + threadIdx.x;
    if (i < N_NODES) g_counts[i] = 0;
}
__global__ void hist_kernel(const void* __restrict__ ei) {
    int e = blockIdx.x * blockDim.x + threadIdx.x;
    if (e >= N_EDGES) return;
    int r = load_eidx(ei, g_idx64, e);
    atomicAdd(&g_counts[r], 1);
}
__global__ void scan_kernel() {
    __shared__ int sh[1024];
    const int PER = 49;
    int t = threadIdx.x;
    int base = t * PER;
    int sum = 0;
    for (int j = 0; j < PER; j++) {
        int idx = base + j;
        if (idx < N_NODES) sum += g_counts[idx];
    }
    sh[t] = sum;
    __syncthreads();
    #pragma unroll
    for (int off = 1; off < 1024; off <<= 1) {
        int add = (t >= off) ? sh[t - off] : 0;
        __syncthreads();
        sh[t] += add;
        __syncthreads();
    }
    int run = sh[t] - sum;
    for (int j = 0; j < PER; j++) {
        int idx = base + j;
        if (idx < N_NODES) {
            g_offsets[idx] = run;
            g_cursor[idx]  = run;
            run += g_counts[idx];
        }
    }
    if (t == 1023) g_offsets[N_NODES] = run;
}
__global__ void scatter_kernel(const void* __restrict__ ei) {
    int e = blockIdx.x * blockDim.x + threadIdx.x;
    if (e >= N_EDGES) return;
    int is64 = g_idx64;
    int r = load_eidx(ei, is64, e);
    int c = load_eidx(ei, is64, (long long)N_EDGES + e);
    int pos = atomicAdd(&g_cursor[r], 1);
    g_scol[pos] = c;
}

// =================== mma.sync bf16 GEMM (R6 design — measured best) ========
#define KWC 16
#define STW 20
#define TILE_W (128 * STW)
#define STAGE_W (4 * TILE_W)
#define CSTRIDE 132
#define GEMM_DYNSMEM (2 * STAGE_W * 4)   // 81920 B

__global__ void __launch_bounds__(256, 2) tc_gemm_kernel(
    const uint32_t* __restrict__ Ahi, const uint32_t* __restrict__ Alo,
    const uint32_t* __restrict__ Bhi, const uint32_t* __restrict__ Blo,
    float* __restrict__ C, int M, int K, int ldc,
    const float* __restrict__ bias, int mode)
{
    extern __shared__ uint32_t smw[];
    int tid = threadIdx.x;
    int wid = tid >> 5;
    int lane = tid & 31;
    int warpM = wid & 1;
    int warpN = wid >> 1;
    int blockRow = blockIdx.y * 128;
    int blockCol = blockIdx.x * 128;
    const int Kw = K >> 1;
    const int nch = K >> 5;

    float acc[4][4][4];
    #pragma unroll
    for (int mt = 0; mt < 4; mt++)
        #pragma unroll
        for (int nt = 0; nt < 4; nt++)
            #pragma unroll
            for (int r = 0; r < 4; r++) acc[mt][nt][r] = 0.f;

    uint32_t sbase = smem_u32(smw);
    int ldRow = tid >> 1;
    int ldHalf = tid & 1;
    uint32_t soB = (uint32_t)(ldRow * STW + ldHalf * 8) * 4;
    size_t aOff = (size_t)(blockRow + ldRow) * Kw + ldHalf * 8;
    size_t bOff = (size_t)(blockCol + ldRow) * Kw + ldHalf * 8;

    auto issue = [&](int c) {
        uint32_t d = sbase + (uint32_t)(c & 1) * (STAGE_W * 4) + soB;
        const uint32_t* a0 = Ahi + aOff + (size_t)c * KWC;
        const uint32_t* a1 = Alo + aOff + (size_t)c * KWC;
        const uint32_t* b0 = Bhi + bOff + (size_t)c * KWC;
        const uint32_t* b1 = Blo + bOff + (size_t)c * KWC;
        CP16(d, a0);                      CP16(d + 16, a0 + 4);
        CP16(d + TILE_W * 4, a1);         CP16(d + TILE_W * 4 + 16, a1 + 4);
        CP16(d + 2 * TILE_W * 4, b0);     CP16(d + 2 * TILE_W * 4 + 16, b0 + 4);
        CP16(d + 3 * TILE_W * 4, b1);     CP16(d + 3 * TILE_W * 4 + 16, b1 + 4);
        CP_COMMIT();
    };

    issue(0);
    CP_WAIT0();
    __syncthreads();

    int aLaneRow = (lane & 7) + ((lane >> 3) & 1) * 8;
    int aLaneColW = (lane >> 4) * 4;
    int bLaneRow = (lane & 7) + (lane >> 4) * 8;
    int bLaneColW = ((lane >> 3) & 1) * 4;
    uint32_t aAddr0 = sbase + ((warpM * 64 + aLaneRow) * STW + aLaneColW) * 4;
    uint32_t bAddr0 = sbase + ((warpN * 32 + bLaneRow) * STW + bLaneColW) * 4
                      + 2 * TILE_W * 4;

    for (int c = 0; c < nch; c++) {
        if (c + 1 < nch) issue(c + 1);

        uint32_t stageOff = (uint32_t)(c & 1) * (STAGE_W * 4);
        #pragma unroll
        for (int ks = 0; ks < 2; ks++) {
            uint32_t kOff = stageOff + ks * 32;
            uint32_t ahi[4][4], alo[4][4], bhi[2][4], blo[2][4];
            #pragma unroll
            for (int mt = 0; mt < 4; mt++) {
                uint32_t a = aAddr0 + kOff + mt * (16 * STW * 4);
                ldsm_x4(ahi[mt], a);
                ldsm_x4(alo[mt], a + TILE_W * 4);
            }
            #pragma unroll
            for (int p = 0; p < 2; p++) {
                uint32_t b = bAddr0 + kOff + p * (16 * STW * 4);
                ldsm_x4(bhi[p], b);
                ldsm_x4(blo[p], b + TILE_W * 4);
            }
            #pragma unroll
            for (int mt = 0; mt < 4; mt++)
                #pragma unroll
                for (int nt = 0; nt < 4; nt++) {
                    const uint32_t* bh = &bhi[nt >> 1][(nt & 1) * 2];
                    const uint32_t* bl = &blo[nt >> 1][(nt & 1) * 2];
                    mma_bf16(acc[mt][nt], ahi[mt], bh);
                    mma_bf16(acc[mt][nt], ahi[mt], bl);
                    mma_bf16(acc[mt][nt], alo[mt], bh);
                }
        }

        if (c + 1 < nch) {
            CP_WAIT0();
            __syncthreads();
        }
    }

    // ---- staged epilogue: acc -> smem (fp32) -> coalesced gmem ----
    __syncthreads();
    float* cs = (float*)smw;
    #pragma unroll
    for (int mt = 0; mt < 4; mt++) {
        int r0 = warpM * 64 + mt * 16 + (lane >> 2);
        #pragma unroll
        for (int nt = 0; nt < 4; nt++) {
            int col = warpN * 32 + nt * 8 + (lane & 3) * 2;
            *(float2*)(cs + r0 * CSTRIDE + col) = make_float2(acc[mt][nt][0], acc[mt][nt][1]);
            *(float2*)(cs + (r0 + 8) * CSTRIDE + col) = make_float2(acc[mt][nt][2], acc[mt][nt][3]);
        }
    }
    __syncthreads();
    #pragma unroll
    for (int kk = 0; kk < 16; kk++) {
        int idx = tid + kk * 256;
        int row = idx >> 5;
        int c4 = (idx & 31) * 4;
        int gr = blockRow + row;
        if (gr < M) {
            float4 v = *(float4*)(cs + row * CSTRIDE + c4);
            float4 bv = *(const float4*)(bias + blockCol + c4);
            if (mode == 0) {
                v.x += bv.x; v.y += bv.y; v.z += bv.z; v.w += bv.w;
            } else {
                float degf = (float)(g_offsets[gr + 1] - g_offsets[gr]);
                v.x += degf * bv.x; v.y += degf * bv.y;
                v.z += degf * bv.z; v.w += degf * bv.w;
            }
            *(float4*)(C + (size_t)gr * ldc + blockCol + c4) = v;
        }
    }
}

// ---------------- aggregation: 2 warps per node, 4-edge unroll --------------
// warp covers half the row (256 floats; 8 floats/lane = 2 float4).
__global__ void __launch_bounds__(256) aggregate_kernel() {
    int gwarp = (blockIdx.x * blockDim.x + threadIdx.x) >> 5;
    int node = gwarp >> 1;
    int half = gwarp & 1;
    int lane = threadIdx.x & 31;
    if (node >= N_NODES) return;

    const float* Abase = g_AB + (size_t)node * D_AB + half * 256 + lane * 8;
    float4 a0 = *(const float4*)Abase;
    float4 a1 = *(const float4*)(Abase + 4);
    float4 s0 = make_float4(0, 0, 0, 0), s1 = s0;

    const size_t bcol = (size_t)(D_H + half * 256 + lane * 8);
    int beg = g_offsets[node], end = g_offsets[node + 1];

    for (int b = beg; b < end; b += 32) {
        int jv = (b + lane < end) ? g_scol[b + lane] : 0;
        int cnt = min(32, end - b);
        int t = 0;
        for (; t + 3 < cnt; t += 4) {
            int j0 = __shfl_sync(0xFFFFFFFFu, jv, t);
            int j1 = __shfl_sync(0xFFFFFFFFu, jv, t + 1);
            int j2 = __shfl_sync(0xFFFFFFFFu, jv, t + 2);
            int j3 = __shfl_sync(0xFFFFFFFFu, jv, t + 3);
            const float* B0 = g_AB + (size_t)j0 * D_AB + bcol;
            const float* B1 = g_AB + (size_t)j1 * D_AB + bcol;
            const float* B2 = g_AB + (size_t)j2 * D_AB + bcol;
            const float* B3 = g_AB + (size_t)j3 * D_AB + bcol;
            float4 p00 = *(const float4*)B0, p01 = *(const float4*)(B0 + 4);
            float4 p10 = *(const float4*)B1, p11 = *(const float4*)(B1 + 4);
            float4 p20 = *(const float4*)B2, p21 = *(const float4*)(B2 + 4);
            float4 p30 = *(const float4*)B3, p31 = *(const float4*)(B3 + 4);
            s0.x += fmaxf(a0.x + p00.x, 0.f) + fmaxf(a0.x + p10.x, 0.f)
                  + fmaxf(a0.x + p20.x, 0.f) + fmaxf(a0.x + p30.x, 0.f);
            s0.y += fmaxf(a0.y + p00.y, 0.f) + fmaxf(a0.y + p10.y, 0.f)
                  + fmaxf(a0.y + p20.y, 0.f) + fmaxf(a0.y + p30.y, 0.f);
            s0.z += fmaxf(a0.z + p00.z, 0.f) + fmaxf(a0.z + p10.z, 0.f)
                  + fmaxf(a0.z + p20.z, 0.f) + fmaxf(a0.z + p30.z, 0.f);
            s0.w += fmaxf(a0.w + p00.w, 0.f) + fmaxf(a0.w + p10.w, 0.f)
                  + fmaxf(a0.w + p20.w, 0.f) + fmaxf(a0.w + p30.w, 0.f);
            s1.x += fmaxf(a1.x + p01.x, 0.f) + fmaxf(a1.x + p11.x, 0.f)
                  + fmaxf(a1.x + p21.x, 0.f) + fmaxf(a1.x + p31.x, 0.f);
            s1.y += fmaxf(a1.y + p01.y, 0.f) + fmaxf(a1.y + p11.y, 0.f)
                  + fmaxf(a1.y + p21.y, 0.f) + fmaxf(a1.y + p31.y, 0.f);
            s1.z += fmaxf(a1.z + p01.z, 0.f) + fmaxf(a1.z + p11.z, 0.f)
                  + fmaxf(a1.z + p21.z, 0.f) + fmaxf(a1.z + p31.z, 0.f);
            s1.w += fmaxf(a1.w + p01.w, 0.f) + fmaxf(a1.w + p11.w, 0.f)
                  + fmaxf(a1.w + p21.w, 0.f) + fmaxf(a1.w + p31.w, 0.f);
        }
        for (; t < cnt; t++) {
            int j0 = __shfl_sync(0xFFFFFFFFu, jv, t);
            const float* B0 = g_AB + (size_t)j0 * D_AB + bcol;
            float4 p00 = *(const float4*)B0, p01 = *(const float4*)(B0 + 4);
            s0.x += fmaxf(a0.x + p00.x, 0.f); s0.y += fmaxf(a0.y + p00.y, 0.f);
            s0.z += fmaxf(a0.z + p00.z, 0.f); s0.w += fmaxf(a0.w + p00.w, 0.f);
            s1.x += fmaxf(a1.x + p01.x, 0.f); s1.y += fmaxf(a1.y + p01.y, 0.f);
            s1.z += fmaxf(a1.z + p01.z, 0.f); s1.w += fmaxf(a1.w + p01.w, 0.f);
        }
    }

    // pack 8 floats -> 4 hi + 4 lo words
    uint4 h, l;
    split2(s0.x, s0.y, h.x, l.x); split2(s0.z, s0.w, h.y, l.y);
    split2(s1.x, s1.y, h.z, l.z); split2(s1.z, s1.w, h.w, l.w);
    size_t so = (size_t)node * (D_H / 2) + half * 128 + lane * 4;
    *(uint4*)(g_Shi + so) = h;
    *(uint4*)(g_Slo + so) = l;
}

// ---------------- launcher --------------------------------------------------
extern "C" void kernel_launch(void* const* d_in, const int* in_sizes, int n_in,
                              void* d_out, int out_size) {
    const float* x   = (const float*)d_in[0];
    const void*  ei  = d_in[1];
    const float* W1  = (const float*)d_in[2];
    const float* b1  = (const float*)d_in[3];
    const float* W2  = (const float*)d_in[4];
    const float* b2  = (const float*)d_in[5];
    float* out = (float*)d_out;

    cudaFuncSetAttribute(tc_gemm_kernel,
                         cudaFuncAttributeMaxDynamicSharedMemorySize, GEMM_DYNSMEM);

    float *gAB, *gB1;
    uint32_t *gXh, *gXl, *gW1h, *gW1l, *gW2h, *gW2l, *gSh, *gSl;
    cudaGetSymbolAddress((void**)&gAB,  g_AB);
    cudaGetSymbolAddress((void**)&gB1,  g_bias1);
    cudaGetSymbolAddress((void**)&gXh,  g_Xhi);
    cudaGetSymbolAddress((void**)&gXl,  g_Xlo);
    cudaGetSymbolAddress((void**)&gW1h, g_WT1hi);
    cudaGetSymbolAddress((void**)&gW1l, g_WT1lo);
    cudaGetSymbolAddress((void**)&gW2h, g_WT2hi);
    cudaGetSymbolAddress((void**)&gW2l, g_WT2lo);
    cudaGetSymbolAddress((void**)&gSh,  g_Shi);
    cudaGetSymbolAddress((void**)&gSl,  g_Slo);

    // launch order keeps GEMM1 in the 4th slot (ncu capture)
    detect_dtype_kernel<<<1, 32>>>((const unsigned*)ei);
    split_x_kernel<<<(N_NODES * 32 + 255) / 256, 256>>>(x);
    build_w1t_kernel<<<(D_AB * (D_F / 2) + 255) / 256, 256>>>(W1, b1);

    // GEMM1 (4th): AB[50000,1024] = x @ WT1^T (+bias_cat)
    {
        dim3 grid(D_AB / 128, N_PAD / 128);
        tc_gemm_kernel<<<grid, 256, GEMM_DYNSMEM>>>(
            gXh, gXl, gW1h, gW1l, gAB, N_NODES, D_F, D_AB, gB1, 0);
    }

    zero_counts_kernel<<<(N_NODES + 255) / 256, 256>>>();
    hist_kernel<<<(N_EDGES + 255) / 256, 256>>>(ei);
    scan_kernel<<<1, 1024>>>();
    scatter_kernel<<<(N_EDGES + 255) / 256, 256>>>(ei);

    aggregate_kernel<<<(N_NODES * 2 * 32 + 255) / 256, 256>>>();
    build_w2t_kernel<<<(D_O * (D_H / 2) + 255) / 256, 256>>>(W2);

    // GEMM2: out[50000,256] = S @ WT2^T + deg*b2
    {
        dim3 grid(D_O / 128, N_PAD / 128);
        tc_gemm_kernel<<<grid, 256, GEMM_DYNSMEM>>>(
            gSh, gSl, gW2h, gW2l, out, N_NODES, D_H, D_O, b2, 1);
    }
}